// round 1
// baseline (speedup 1.0000x reference)
#include <cuda_runtime.h>
#include <cstdio>

// Problem maxima (fixed by dataset: 50000 nodes, feat 512 -> 256 -> 64, 800k edges)
#define MAXN   50000
#define FHID   256
#define FOUT   64

// Scratch (device globals: allocation-free per harness rules)
__device__ float g_h1[MAXN * FHID];   // x @ W1              [N, 256]
__device__ float g_h2[MAXN * FHID];   // spmm(h1) + b1       [N, 256] (relu applied on read)
__device__ float g_h3[MAXN * FOUT];   // relu(h2) @ W2       [N, 64]

// ---------------------------------------------------------------------------
// f32x2 packed math helpers (sm_100+; ptxas never auto-fuses these)
// ---------------------------------------------------------------------------
__device__ __forceinline__ unsigned long long pack2(float lo, float hi) {
    unsigned long long r;
    asm("mov.b64 %0, {%1, %2};" : "=l"(r) : "f"(lo), "f"(hi));
    return r;
}
__device__ __forceinline__ unsigned long long ffma2(unsigned long long a,
                                                    unsigned long long b,
                                                    unsigned long long c) {
    unsigned long long d;
    asm("fma.rn.f32x2 %0, %1, %2, %3;" : "=l"(d) : "l"(a), "l"(b), "l"(c));
    return d;
}
__device__ __forceinline__ float2 unpack2(unsigned long long v) {
    float2 f;
    asm("mov.b64 {%0, %1}, %2;" : "=f"(f.x), "=f"(f.y) : "l"(v));
    return f;
}

// ---------------------------------------------------------------------------
// SGEMM: C[M,N] = op(A)[M,K] @ B[K,N], all row-major, fp32 with f32x2 FMA.
// BM=128, BN=64, BK=16, 256 threads, each thread 8x4 outputs (4 M-pairs x 4 N).
// RELU: apply relu to A elements on load (fuses relu(h2) into GEMM2).
// Requires: N % 64 == 0, K % 16 == 0 (true: N in {256,64}, K in {512,256}).
// ---------------------------------------------------------------------------
template<bool RELU>
__global__ void __launch_bounds__(256)
sgemm128x64(const float* __restrict__ A, const float* __restrict__ B,
            float* __restrict__ C, int M, int N, int K)
{
    constexpr int BM = 128, BN = 64, BK = 16;
    __shared__ float As[BK][BM];   // transposed A tile
    __shared__ float Bs[BK][BN];

    const int tid = threadIdx.x;
    const int tx  = tid & 15;      // N direction (16 x TN=4)
    const int ty  = tid >> 4;      // M direction (16 x TM=8)
    const int m0  = ty * 8;
    const int n0  = tx * 4;
    const int blockM = blockIdx.y * BM;
    const int blockN = blockIdx.x * BN;

    unsigned long long acc[4][4];  // [m-pair][n], each = packed {f32,f32}
    #pragma unroll
    for (int i = 0; i < 4; i++)
        #pragma unroll
        for (int j = 0; j < 4; j++) acc[i][j] = 0ull;   // bits of {+0.f,+0.f}

    const int br = tid >> 4;            // B tile row 0..15
    const int bn = (tid & 15) << 2;     // B tile col (float4)

    for (int k0 = 0; k0 < K; k0 += BK) {
        // --- load A tile (128x16) : 2 float4 per thread, store transposed ---
        #pragma unroll
        for (int it = 0; it < 2; it++) {
            int idx = tid + it * 256;       // 0..511
            int ar  = idx >> 2;             // row within tile 0..127
            int ak  = (idx & 3) << 2;       // k offset within tile {0,4,8,12}
            int m   = blockM + ar;
            float4 v = make_float4(0.f, 0.f, 0.f, 0.f);
            if (m < M)
                v = *reinterpret_cast<const float4*>(&A[(size_t)m * K + k0 + ak]);
            if (RELU) {
                v.x = fmaxf(v.x, 0.f); v.y = fmaxf(v.y, 0.f);
                v.z = fmaxf(v.z, 0.f); v.w = fmaxf(v.w, 0.f);
            }
            As[ak + 0][ar] = v.x; As[ak + 1][ar] = v.y;
            As[ak + 2][ar] = v.z; As[ak + 3][ar] = v.w;
        }
        // --- load B tile (16x64) : 1 float4 per thread ---
        {
            float4 v = *reinterpret_cast<const float4*>(
                &B[(size_t)(k0 + br) * N + blockN + bn]);
            *reinterpret_cast<float4*>(&Bs[br][bn]) = v;
        }
        __syncthreads();

        #pragma unroll
        for (int kk = 0; kk < BK; kk++) {
            unsigned long long a2[4];
            #pragma unroll
            for (int i = 0; i < 4; i++)
                a2[i] = *reinterpret_cast<const unsigned long long*>(
                            &As[kk][m0 + 2 * i]);   // 8B-aligned (m0 % 8 == 0)
            float4 bv = *reinterpret_cast<const float4*>(&Bs[kk][n0]);
            unsigned long long bp0 = pack2(bv.x, bv.x);
            unsigned long long bp1 = pack2(bv.y, bv.y);
            unsigned long long bp2 = pack2(bv.z, bv.z);
            unsigned long long bp3 = pack2(bv.w, bv.w);
            #pragma unroll
            for (int i = 0; i < 4; i++) {
                acc[i][0] = ffma2(a2[i], bp0, acc[i][0]);
                acc[i][1] = ffma2(a2[i], bp1, acc[i][1]);
                acc[i][2] = ffma2(a2[i], bp2, acc[i][2]);
                acc[i][3] = ffma2(a2[i], bp3, acc[i][3]);
            }
        }
        __syncthreads();
    }

    // --- epilogue: 2 float4 stores per m-pair ---
    #pragma unroll
    for (int i = 0; i < 4; i++) {
        float2 v0 = unpack2(acc[i][0]);
        float2 v1 = unpack2(acc[i][1]);
        float2 v2 = unpack2(acc[i][2]);
        float2 v3 = unpack2(acc[i][3]);
        int m_lo = blockM + m0 + 2 * i;
        if (m_lo < M)
            *reinterpret_cast<float4*>(&C[(size_t)m_lo * N + blockN + n0]) =
                make_float4(v0.x, v1.x, v2.x, v3.x);
        if (m_lo + 1 < M)
            *reinterpret_cast<float4*>(&C[(size_t)(m_lo + 1) * N + blockN + n0]) =
                make_float4(v0.y, v1.y, v2.y, v3.y);
    }
}

// ---------------------------------------------------------------------------
// dst[i] = bias[i % F]   (F power of two; mask passed as F-1)
// ---------------------------------------------------------------------------
__global__ void init_bias_kernel(float* __restrict__ dst,
                                 const float* __restrict__ bias,
                                 int total, int fmask)
{
    int i = blockIdx.x * blockDim.x + threadIdx.x;
    if (i < total) dst[i] = bias[i & fmask];
}

// ---------------------------------------------------------------------------
// SpMM scatter: dst[row[e]] += edge_w[e] * src[col[e]], row sorted ascending.
// F threads per feature-group, G groups per 256-thread block, EPG edges/group.
// Register accumulation across the sorted-row run; atomicAdd only at row
// changes / chunk boundaries (~56k flushes instead of 205M atomics).
// ---------------------------------------------------------------------------
template<int F, int EPG, int G>
__global__ void __launch_bounds__(F * G)
spmm_scatter(const float* __restrict__ src, const float* __restrict__ ew,
             const int* __restrict__ row, const int* __restrict__ col,
             float* __restrict__ dst, int E)
{
    __shared__ int   s_row[G][EPG];
    __shared__ int   s_col[G][EPG];
    __shared__ float s_w[G][EPG];

    const int g = threadIdx.x / F;
    const int f = threadIdx.x % F;
    const long base = ((long)blockIdx.x * G + g) * EPG;

    long rem = (long)E - base;
    const int cnt = rem <= 0 ? 0 : (rem < EPG ? (int)rem : EPG);

    for (int i = f; i < cnt; i += F) {
        long e = base + i;
        s_row[g][i] = row[e];
        s_col[g][i] = col[e];
        s_w[g][i]   = ew[e];
    }
    __syncthreads();

    float acc = 0.f;
    int   cur = -1;
    #pragma unroll 4
    for (int i = 0; i < cnt; ++i) {
        int   r = s_row[g][i];
        int   c = s_col[g][i];
        float w = s_w[g][i];
        float v = w * __ldg(&src[(size_t)c * F + f]);
        if (r != cur) {
            if (cur >= 0) atomicAdd(&dst[(size_t)cur * F + f], acc);
            cur = r;
            acc = 0.f;
        }
        acc += v;
    }
    if (cur >= 0) atomicAdd(&dst[(size_t)cur * F + f], acc);
}

// ---------------------------------------------------------------------------
extern "C" void kernel_launch(void* const* d_in, const int* in_sizes, int n_in,
                              void* d_out, int out_size)
{
    const float* x   = (const float*)d_in[0];
    const float* w1  = (const float*)d_in[1];
    const float* b1  = (const float*)d_in[2];
    const float* w2  = (const float*)d_in[3];
    const float* b2  = (const float*)d_in[4];
    const float* ew  = (const float*)d_in[5];
    const int*   row = (const int*)d_in[6];
    const int*   col = (const int*)d_in[7];

    const int nhid  = in_sizes[2];            // 256
    const int nout  = in_sizes[4];            // 64
    const int nfeat = in_sizes[1] / nhid;     // 512
    const int n     = in_sizes[0] / nfeat;    // 50000
    const int E     = in_sizes[5];            // 800000

    void *p1, *p2, *p3;
    cudaGetSymbolAddress(&p1, g_h1);
    cudaGetSymbolAddress(&p2, g_h2);
    cudaGetSymbolAddress(&p3, g_h3);
    float* h1 = (float*)p1;
    float* h2 = (float*)p2;
    float* h3 = (float*)p3;
    float* out = (float*)d_out;

    // 1) h1 = x @ W1
    {
        dim3 grid((nhid + 63) / 64, (n + 127) / 128);
        sgemm128x64<false><<<grid, 256>>>(x, w1, h1, n, nhid, nfeat);
    }
    // 2) h2 = b1 (broadcast), then h2 += scatter(edge_w * h1[col]) into row
    {
        int total = n * nhid;
        init_bias_kernel<<<(total + 255) / 256, 256>>>(h2, b1, total, nhid - 1);
        int blocks = (E + 256 - 1) / 256;                   // F=256, G=1, EPG=256
        spmm_scatter<256, 256, 1><<<blocks, 256>>>(h1, ew, row, col, h2, E);
    }
    // 3) h3 = relu(h2) @ W2   (relu fused into A-tile load)
    {
        dim3 grid((nout + 63) / 64, (n + 127) / 128);
        sgemm128x64<true><<<grid, 256>>>(h2, w2, h3, n, nout, nhid);
    }
    // 4) out = b2 (broadcast), then out += scatter(edge_w * h3[col])
    {
        int total = n * nout;
        init_bias_kernel<<<(total + 255) / 256, 256>>>(out, b2, total, nout - 1);
        int blocks = (E + 256 * 4 - 1) / (256 * 4);         // F=64, G=4, EPG=256
        spmm_scatter<64, 256, 4><<<blocks, 256>>>(h3, ew, row, col, out, E);
    }
}

// round 3
// speedup vs baseline: 1.5676x; 1.5676x over previous
#include <cuda_runtime.h>
#include <cstdint>

// Problem constants (fixed by dataset)
#define MAXN   50000
#define NFEAT  512
#define FHID   256
#define FOUT   64

// Scratch (device globals: allocation-free per harness rules)
__device__ float g_h1 [MAXN * FHID];    // x @ W1
__device__ float g_h2 [MAXN * FHID];    // spmm(h1) + b1 -> relu+tf32-round in place
__device__ float g_h3 [MAXN * FOUT];    // relu(h2) @ W2
__device__ float g_w1t[FHID * NFEAT];   // W1^T, tf32-rounded
__device__ float g_w2t[FOUT * FHID];    // W2^T, tf32-rounded

// ===========================================================================
// helpers
// ===========================================================================
__device__ __forceinline__ uint32_t smem_u32(const void* p) {
    uint32_t a;
    asm("{ .reg .u64 t; cvta.to.shared.u64 t, %1; cvt.u32.u64 %0, t; }"
        : "=r"(a) : "l"(p));
    return a;
}
__device__ __forceinline__ float rna_tf32(float f) {
    uint32_t u;
    asm("cvt.rna.tf32.f32 %0, %1;" : "=r"(u) : "f"(f));
    return __uint_as_float(u);
}
__device__ __forceinline__ void cp16(uint32_t dst, const void* src) {
    asm volatile("cp.async.cg.shared.global [%0], [%1], 16;"
                 :: "r"(dst), "l"(src) : "memory");
}
#define CP_COMMIT() asm volatile("cp.async.commit_group;" ::: "memory")
#define CP_WAIT0()  asm volatile("cp.async.wait_group 0;" ::: "memory")

// mma.sync m16n8k8 tf32 (base PTX, works on compute_103 target)
__device__ __forceinline__ void mma8(float* d, const uint32_t* a, const uint32_t* b) {
    asm volatile(
        "mma.sync.aligned.m16n8k8.row.col.f32.tf32.tf32.f32 "
        "{%0,%1,%2,%3}, {%4,%5,%6,%7}, {%8,%9}, {%0,%1,%2,%3};"
        : "+f"(d[0]), "+f"(d[1]), "+f"(d[2]), "+f"(d[3])
        : "r"(a[0]), "r"(a[1]), "r"(a[2]), "r"(a[3]), "r"(b[0]), "r"(b[1]));
}

// ===========================================================================
// tf32 tensor-core GEMM:  C[M, Ntot] = A[M,K] @ Bt[Ntot,K]^T
//   BM=128, BN template (128 or 64), BK=16; 256 threads = 8 warps (2M x 4N);
//   warp tile 64 x (BN/4); A register-staged (+ optional rna-tf32 cvt),
//   B via cp.async (pre-rounded); double-buffered SMEM, row stride 20 floats
//   (16B aligned for cp.async; conflict-free LDS.32 fragment loads).
// ===========================================================================
template<int BN, int WNT, bool CVT_A>
__global__ void __launch_bounds__(256)
gemm_mma(const float* __restrict__ A, const float* __restrict__ Bt,
         float* __restrict__ C, int M, int K, int Ntot)
{
    constexpr int BM = 128, BK = 16, LDS = 20;
    constexpr int NBI = (BN * BK / 4) / 256;      // B float4 per thread (2 or 1)
    __shared__ float As[2][BM * LDS];
    __shared__ float Bs[2][BN * LDS];

    const int tid  = threadIdx.x;
    const int lane = tid & 31, wid = tid >> 5;
    const int g    = lane >> 2, tig = lane & 3;
    const int wm0  = (wid >> 2) * 64;             // warp M origin (0/64)
    const int wn0  = (wid & 3) * (BN / 4);        // warp N origin
    const int blockM = blockIdx.y * BM;
    const int blockN = blockIdx.x * BN;

    const int arow = tid >> 2;                    // 0..63  (A rows: arow, arow+64)
    const int aq   = tid & 3;                     // which float4 within 16-col row

    float acc[4][WNT][4];
    #pragma unroll
    for (int mt = 0; mt < 4; mt++)
        #pragma unroll
        for (int nt = 0; nt < WNT; nt++)
            #pragma unroll
            for (int i = 0; i < 4; i++) acc[mt][nt][i] = 0.f;

    auto ldgA = [&](int c, float4* av) {
        const int k0 = c * BK;
        #pragma unroll
        for (int i = 0; i < 2; i++) {
            int r = blockM + arow + i * 64;
            if (r < M)
                av[i] = *reinterpret_cast<const float4*>(&A[(size_t)r * K + k0 + aq * 4]);
            else
                av[i] = make_float4(0.f, 0.f, 0.f, 0.f);
        }
    };
    auto stsA = [&](int buf, float4* av) {
        #pragma unroll
        for (int i = 0; i < 2; i++) {
            float4 v = av[i];
            if (CVT_A) {
                v.x = rna_tf32(v.x); v.y = rna_tf32(v.y);
                v.z = rna_tf32(v.z); v.w = rna_tf32(v.w);
            }
            *reinterpret_cast<float4*>(&As[buf][(arow + i * 64) * LDS + aq * 4]) = v;
        }
    };
    auto cpB = [&](int c, int buf) {
        const int k0 = c * BK;
        #pragma unroll
        for (int i = 0; i < NBI; i++) {
            int u = tid + i * 256;
            int r = u >> 2, q = u & 3;
            cp16(smem_u32(&Bs[buf][r * LDS + q * 4]),
                 &Bt[(size_t)(blockN + r) * K + k0 + q * 4]);
        }
        CP_COMMIT();
    };
    auto compute = [&](int buf) {
        #pragma unroll
        for (int ks = 0; ks < 2; ks++) {
            uint32_t a[4][4], b[WNT][2];
            #pragma unroll
            for (int mt = 0; mt < 4; mt++) {
                const float* p0 = &As[buf][(wm0 + mt * 16 + g) * LDS + ks * 8];
                const float* p1 = p0 + 8 * LDS;
                a[mt][0] = __float_as_uint(p0[tig]);
                a[mt][2] = __float_as_uint(p0[tig + 4]);
                a[mt][1] = __float_as_uint(p1[tig]);
                a[mt][3] = __float_as_uint(p1[tig + 4]);
            }
            #pragma unroll
            for (int nt = 0; nt < WNT; nt++) {
                const float* pb = &Bs[buf][(wn0 + nt * 8 + g) * LDS + ks * 8];
                b[nt][0] = __float_as_uint(pb[tig]);
                b[nt][1] = __float_as_uint(pb[tig + 4]);
            }
            #pragma unroll
            for (int mt = 0; mt < 4; mt++)
                #pragma unroll
                for (int nt = 0; nt < WNT; nt++)
                    mma8(acc[mt][nt], a[mt], b[nt]);
        }
    };

    // prologue: fill buffer 0
    {
        float4 av[2];
        ldgA(0, av);
        cpB(0, 0);
        stsA(0, av);
        CP_WAIT0();
        __syncthreads();
    }

    const int NC = K / BK;
    for (int c = 0; c < NC; c++) {
        float4 av[2];
        const bool more = (c + 1 < NC);
        if (more) {
            ldgA(c + 1, av);           // global latency overlapped with compute
            cpB(c + 1, (c + 1) & 1);
        }
        compute(c & 1);
        if (more) {
            stsA((c + 1) & 1, av);
            CP_WAIT0();
            __syncthreads();
        }
    }

    // epilogue
    #pragma unroll
    for (int mt = 0; mt < 4; mt++) {
        int r0 = blockM + wm0 + mt * 16 + g;
        int r1 = r0 + 8;
        #pragma unroll
        for (int nt = 0; nt < WNT; nt++) {
            int cb = blockN + wn0 + nt * 8 + 2 * tig;
            if (r0 < M)
                *reinterpret_cast<float2*>(&C[(size_t)r0 * Ntot + cb]) =
                    make_float2(acc[mt][nt][0], acc[mt][nt][1]);
            if (r1 < M)
                *reinterpret_cast<float2*>(&C[(size_t)r1 * Ntot + cb]) =
                    make_float2(acc[mt][nt][2], acc[mt][nt][3]);
        }
    }
}

// ===========================================================================
// Small elementwise / transpose kernels
// ===========================================================================
__global__ void transpose_round(const float* __restrict__ in, float* __restrict__ out,
                                int Krows, int Ncols)
{
    int i = blockIdx.x * blockDim.x + threadIdx.x;
    if (i < Krows * Ncols) {
        int k = i / Ncols, n = i % Ncols;
        out[(size_t)n * Krows + k] = rna_tf32(in[i]);
    }
}

__global__ void relu_round4(float* __restrict__ h, int n4)
{
    int i = blockIdx.x * blockDim.x + threadIdx.x;
    if (i < n4) {
        float4 v = reinterpret_cast<float4*>(h)[i];
        v.x = rna_tf32(fmaxf(v.x, 0.f));
        v.y = rna_tf32(fmaxf(v.y, 0.f));
        v.z = rna_tf32(fmaxf(v.z, 0.f));
        v.w = rna_tf32(fmaxf(v.w, 0.f));
        reinterpret_cast<float4*>(h)[i] = v;
    }
}

__global__ void init_bias_kernel(float* __restrict__ dst, const float* __restrict__ bias,
                                 int total, int fmask)
{
    int i = blockIdx.x * blockDim.x + threadIdx.x;
    if (i < total) dst[i] = bias[i & fmask];
}

// ---------------------------------------------------------------------------
// SpMM scatter: dst[row[e]] += edge_w[e] * src[col[e]], row sorted ascending.
// ---------------------------------------------------------------------------
template<int F, int EPG, int G>
__global__ void __launch_bounds__(F * G)
spmm_scatter(const float* __restrict__ src, const float* __restrict__ ew,
             const int* __restrict__ row, const int* __restrict__ col,
             float* __restrict__ dst, int E)
{
    __shared__ int   s_row[G][EPG];
    __shared__ int   s_col[G][EPG];
    __shared__ float s_w[G][EPG];

    const int g = threadIdx.x / F;
    const int f = threadIdx.x % F;
    const long base = ((long)blockIdx.x * G + g) * EPG;

    long rem = (long)E - base;
    const int cnt = rem <= 0 ? 0 : (rem < EPG ? (int)rem : EPG);

    for (int i = f; i < cnt; i += F) {
        long e = base + i;
        s_row[g][i] = row[e];
        s_col[g][i] = col[e];
        s_w[g][i]   = ew[e];
    }
    __syncthreads();

    float acc = 0.f;
    int   cur = -1;
    #pragma unroll 4
    for (int i = 0; i < cnt; ++i) {
        int   r = s_row[g][i];
        int   c = s_col[g][i];
        float w = s_w[g][i];
        float v = w * __ldg(&src[(size_t)c * F + f]);
        if (r != cur) {
            if (cur >= 0) atomicAdd(&dst[(size_t)cur * F + f], acc);
            cur = r;
            acc = 0.f;
        }
        acc += v;
    }
    if (cur >= 0) atomicAdd(&dst[(size_t)cur * F + f], acc);
}

// ===========================================================================
extern "C" void kernel_launch(void* const* d_in, const int* in_sizes, int n_in,
                              void* d_out, int out_size)
{
    const float* x   = (const float*)d_in[0];
    const float* w1  = (const float*)d_in[1];
    const float* b1  = (const float*)d_in[2];
    const float* w2  = (const float*)d_in[3];
    const float* b2  = (const float*)d_in[4];
    const float* ew  = (const float*)d_in[5];
    const int*   row = (const int*)d_in[6];
    const int*   col = (const int*)d_in[7];

    const int nhid  = in_sizes[2];            // 256
    const int nout  = in_sizes[4];            // 64
    const int nfeat = in_sizes[1] / nhid;     // 512
    const int n     = in_sizes[0] / nfeat;    // 50000
    const int E     = in_sizes[5];            // 800000

    void *p1, *p2, *p3, *p4, *p5;
    cudaGetSymbolAddress(&p1, g_h1);
    cudaGetSymbolAddress(&p2, g_h2);
    cudaGetSymbolAddress(&p3, g_h3);
    cudaGetSymbolAddress(&p4, g_w1t);
    cudaGetSymbolAddress(&p5, g_w2t);
    float* h1  = (float*)p1;
    float* h2  = (float*)p2;
    float* h3  = (float*)p3;
    float* w1t = (float*)p4;
    float* w2t = (float*)p5;
    float* out = (float*)d_out;

    const int tilesM = (n + 127) / 128;                   // 391

    // 0) W transposes (+ tf32 RN rounding)
    transpose_round<<<(nfeat * nhid + 255) / 256, 256>>>(w1, w1t, nfeat, nhid);
    transpose_round<<<(nhid * nout + 255) / 256, 256>>>(w2, w2t, nhid, nout);

    // 1) h1 = x @ W1   (mma.sync tf32; A rounded in registers)
    {
        dim3 grid(nhid / 128, tilesM);
        gemm_mma<128, 4, true><<<grid, 256>>>(x, w1t, h1, n, nfeat, nhid);
    }

    // 2) h2 = b1 + scatter(edge_w * h1[col]) into row
    {
        int total = n * nhid;
        init_bias_kernel<<<(total + 255) / 256, 256>>>(h2, b1, total, nhid - 1);
        spmm_scatter<256, 256, 1><<<(E + 255) / 256, 256>>>(h1, ew, row, col, h2, E);
    }

    // 3) h2 = rna_tf32(relu(h2)) in place; h3 = h2 @ W2
    {
        int n4 = n * nhid / 4;
        relu_round4<<<(n4 + 255) / 256, 256>>>(h2, n4);
        dim3 grid(nout / 64, tilesM);
        gemm_mma<64, 2, false><<<grid, 256>>>(h2, w2t, h3, n, nhid, nout);
    }

    // 4) out = b2 + scatter(edge_w * h3[col])
    {
        int total = n * nout;
        init_bias_kernel<<<(total + 255) / 256, 256>>>(out, b2, total, nout - 1);
        spmm_scatter<64, 256, 4><<<(E + 1023) / 1024, 256>>>(h3, ew, row, col, out, E);
    }
}

// round 4
// speedup vs baseline: 1.9246x; 1.2277x over previous
#include <cuda_runtime.h>
#include <cstdint>

// Problem constants (fixed by dataset)
#define MAXN   50000
#define NFEAT  512
#define FHID   256
#define FOUT   64

// Scratch (device globals: allocation-free per harness rules)
__device__ float g_h1 [MAXN * FHID];    // x @ W1
__device__ float g_h2 [MAXN * FHID];    // spmm(h1) + b1 -> relu+tf32-round in place
__device__ float g_h3 [MAXN * FOUT];    // relu(h2) @ W2
__device__ float g_w1t[FHID * NFEAT];   // W1^T, tf32-rounded
__device__ float g_w2t[FOUT * FHID];    // W2^T, tf32-rounded

// ===========================================================================
// helpers
// ===========================================================================
__device__ __forceinline__ uint32_t smem_u32(const void* p) {
    uint32_t a;
    asm("{ .reg .u64 t; cvta.to.shared.u64 t, %1; cvt.u32.u64 %0, t; }"
        : "=r"(a) : "l"(p));
    return a;
}
__device__ __forceinline__ float rna_tf32(float f) {
    uint32_t u;
    asm("cvt.rna.tf32.f32 %0, %1;" : "=r"(u) : "f"(f));
    return __uint_as_float(u);
}
__device__ __forceinline__ void cp16(uint32_t dst, const void* src) {
    asm volatile("cp.async.cg.shared.global [%0], [%1], 16;"
                 :: "r"(dst), "l"(src) : "memory");
}
#define CP_COMMIT() asm volatile("cp.async.commit_group;" ::: "memory")
#define CP_WAIT0()  asm volatile("cp.async.wait_group 0;" ::: "memory")

// mma.sync m16n8k8 tf32 (base PTX, works on compute_103 target)
__device__ __forceinline__ void mma8(float* d, const uint32_t* a, const uint32_t* b) {
    asm volatile(
        "mma.sync.aligned.m16n8k8.row.col.f32.tf32.tf32.f32 "
        "{%0,%1,%2,%3}, {%4,%5,%6,%7}, {%8,%9}, {%0,%1,%2,%3};"
        : "+f"(d[0]), "+f"(d[1]), "+f"(d[2]), "+f"(d[3])
        : "r"(a[0]), "r"(a[1]), "r"(a[2]), "r"(a[3]), "r"(b[0]), "r"(b[1]));
}

// ===========================================================================
// tf32 tensor-core GEMM:  C[M, Ntot] = A[M,K] @ Bt[Ntot,K]^T
//   BM=128, BN template (128 or 64), BK=16; 256 threads = 8 warps (2M x 4N);
//   warp tile 64 x (BN/4); A register-staged (+ optional rna-tf32 cvt),
//   B via cp.async (pre-rounded); double-buffered SMEM, row stride 20 floats.
// ===========================================================================
template<int BN, int WNT, bool CVT_A>
__global__ void __launch_bounds__(256)
gemm_mma(const float* __restrict__ A, const float* __restrict__ Bt,
         float* __restrict__ C, int M, int K, int Ntot)
{
    constexpr int BM = 128, BK = 16, LDS = 20;
    constexpr int NBI = (BN * BK / 4) / 256;      // B float4 per thread (2 or 1)
    __shared__ float As[2][BM * LDS];
    __shared__ float Bs[2][BN * LDS];

    const int tid  = threadIdx.x;
    const int lane = tid & 31, wid = tid >> 5;
    const int g    = lane >> 2, tig = lane & 3;
    const int wm0  = (wid >> 2) * 64;             // warp M origin (0/64)
    const int wn0  = (wid & 3) * (BN / 4);        // warp N origin
    const int blockM = blockIdx.y * BM;
    const int blockN = blockIdx.x * BN;

    const int arow = tid >> 2;                    // 0..63  (A rows: arow, arow+64)
    const int aq   = tid & 3;                     // which float4 within 16-col row

    float acc[4][WNT][4];
    #pragma unroll
    for (int mt = 0; mt < 4; mt++)
        #pragma unroll
        for (int nt = 0; nt < WNT; nt++)
            #pragma unroll
            for (int i = 0; i < 4; i++) acc[mt][nt][i] = 0.f;

    auto ldgA = [&](int c, float4* av) {
        const int k0 = c * BK;
        #pragma unroll
        for (int i = 0; i < 2; i++) {
            int r = blockM + arow + i * 64;
            if (r < M)
                av[i] = *reinterpret_cast<const float4*>(&A[(size_t)r * K + k0 + aq * 4]);
            else
                av[i] = make_float4(0.f, 0.f, 0.f, 0.f);
        }
    };
    auto stsA = [&](int buf, float4* av) {
        #pragma unroll
        for (int i = 0; i < 2; i++) {
            float4 v = av[i];
            if (CVT_A) {
                v.x = rna_tf32(v.x); v.y = rna_tf32(v.y);
                v.z = rna_tf32(v.z); v.w = rna_tf32(v.w);
            }
            *reinterpret_cast<float4*>(&As[buf][(arow + i * 64) * LDS + aq * 4]) = v;
        }
    };
    auto cpB = [&](int c, int buf) {
        const int k0 = c * BK;
        #pragma unroll
        for (int i = 0; i < NBI; i++) {
            int u = tid + i * 256;
            int r = u >> 2, q = u & 3;
            cp16(smem_u32(&Bs[buf][r * LDS + q * 4]),
                 &Bt[(size_t)(blockN + r) * K + k0 + q * 4]);
        }
        CP_COMMIT();
    };
    auto compute = [&](int buf) {
        #pragma unroll
        for (int ks = 0; ks < 2; ks++) {
            uint32_t a[4][4], b[WNT][2];
            #pragma unroll
            for (int mt = 0; mt < 4; mt++) {
                const float* p0 = &As[buf][(wm0 + mt * 16 + g) * LDS + ks * 8];
                const float* p1 = p0 + 8 * LDS;
                a[mt][0] = __float_as_uint(p0[tig]);
                a[mt][2] = __float_as_uint(p0[tig + 4]);
                a[mt][1] = __float_as_uint(p1[tig]);
                a[mt][3] = __float_as_uint(p1[tig + 4]);
            }
            #pragma unroll
            for (int nt = 0; nt < WNT; nt++) {
                const float* pb = &Bs[buf][(wn0 + nt * 8 + g) * LDS + ks * 8];
                b[nt][0] = __float_as_uint(pb[tig]);
                b[nt][1] = __float_as_uint(pb[tig + 4]);
            }
            #pragma unroll
            for (int mt = 0; mt < 4; mt++)
                #pragma unroll
                for (int nt = 0; nt < WNT; nt++)
                    mma8(acc[mt][nt], a[mt], b[nt]);
        }
    };

    // prologue: fill buffer 0
    {
        float4 av[2];
        ldgA(0, av);
        cpB(0, 0);
        stsA(0, av);
        CP_WAIT0();
        __syncthreads();
    }

    const int NC = K / BK;
    for (int c = 0; c < NC; c++) {
        float4 av[2];
        const bool more = (c + 1 < NC);
        if (more) {
            ldgA(c + 1, av);           // global latency overlapped with compute
            cpB(c + 1, (c + 1) & 1);
        }
        compute(c & 1);
        if (more) {
            stsA((c + 1) & 1, av);
            CP_WAIT0();
            __syncthreads();
        }
    }

    // epilogue
    #pragma unroll
    for (int mt = 0; mt < 4; mt++) {
        int r0 = blockM + wm0 + mt * 16 + g;
        int r1 = r0 + 8;
        #pragma unroll
        for (int nt = 0; nt < WNT; nt++) {
            int cb = blockN + wn0 + nt * 8 + 2 * tig;
            if (r0 < M)
                *reinterpret_cast<float2*>(&C[(size_t)r0 * Ntot + cb]) =
                    make_float2(acc[mt][nt][0], acc[mt][nt][1]);
            if (r1 < M)
                *reinterpret_cast<float2*>(&C[(size_t)r1 * Ntot + cb]) =
                    make_float2(acc[mt][nt][2], acc[mt][nt][3]);
        }
    }
}

// ===========================================================================
// Elementwise kernels
// ===========================================================================
// Both weight transposes (+ tf32 RN rounding) in one launch.
__global__ void transpose_round2(const float* __restrict__ w1, float* __restrict__ w1t,
                                 const float* __restrict__ w2, float* __restrict__ w2t,
                                 int sz1, int n1, int k1, int sz2, int n2, int k2)
{
    int i = blockIdx.x * blockDim.x + threadIdx.x;
    if (i < sz1) {
        int k = i / n1, n = i % n1;
        w1t[(size_t)n * k1 + k] = rna_tf32(w1[i]);
    } else if (i < sz1 + sz2) {
        int j = i - sz1;
        int k = j / n2, n = j % n2;
        w2t[(size_t)n * k2 + k] = rna_tf32(w2[j]);
    }
}

__global__ void relu_round4(float* __restrict__ h, int n4)
{
    int i = blockIdx.x * blockDim.x + threadIdx.x;
    if (i < n4) {
        float4 v = reinterpret_cast<float4*>(h)[i];
        v.x = rna_tf32(fmaxf(v.x, 0.f));
        v.y = rna_tf32(fmaxf(v.y, 0.f));
        v.z = rna_tf32(fmaxf(v.z, 0.f));
        v.w = rna_tf32(fmaxf(v.w, 0.f));
        reinterpret_cast<float4*>(h)[i] = v;
    }
}

// dst4[i] = bias4[i mod (F/4)], vectorized bias broadcast (~4x fewer stores)
__global__ void init_bias4(float4* __restrict__ dst, const float4* __restrict__ bias,
                           int total4, int fmask4)
{
    int i = blockIdx.x * blockDim.x + threadIdx.x;
    if (i < total4) dst[i] = bias[i & fmask4];
}

// ---------------------------------------------------------------------------
// SpMM scatter: dst[row[e]] += edge_w[e] * src[col[e]], row sorted ascending.
// Batched-8 gather (explicit MLP=8), register accumulation across sorted-row
// runs, atomicAdd only at row changes / chunk boundaries.
// ---------------------------------------------------------------------------
template<int F, int EPG, int G>
__global__ void __launch_bounds__(F * G)
spmm_scatter(const float* __restrict__ src, const float* __restrict__ ew,
             const int* __restrict__ row, const int* __restrict__ col,
             float* __restrict__ dst, int E)
{
    __shared__ int   s_row[G][EPG];
    __shared__ int   s_col[G][EPG];
    __shared__ float s_w[G][EPG];

    const int g = threadIdx.x / F;
    const int f = threadIdx.x % F;
    const long base = ((long)blockIdx.x * G + g) * EPG;

    long rem = (long)E - base;
    const int cnt = rem <= 0 ? 0 : (rem < EPG ? (int)rem : EPG);

    for (int i = f; i < cnt; i += F) {
        long e = base + i;
        s_row[g][i] = row[e];
        s_col[g][i] = col[e];
        s_w[g][i]   = ew[e];
    }
    __syncthreads();

    const float* srcf = src + f;
    float acc = 0.f;
    int   cur = -1;

    int i = 0;
    const int full = cnt & ~7;
    for (; i < full; i += 8) {
        int   rr[8];
        float v[8];
        #pragma unroll
        for (int j = 0; j < 8; j++) {               // 8 gathers in flight
            rr[j] = s_row[g][i + j];
            v[j]  = s_w[g][i + j] *
                    __ldg(&srcf[(size_t)s_col[g][i + j] * F]);
        }
        #pragma unroll
        for (int j = 0; j < 8; j++) {               // register-only scan
            if (rr[j] != cur) {
                if (cur >= 0) atomicAdd(&dst[(size_t)cur * F + f], acc);
                cur = rr[j];
                acc = 0.f;
            }
            acc += v[j];
        }
    }
    for (; i < cnt; i++) {
        int   r = s_row[g][i];
        float v = s_w[g][i] * __ldg(&srcf[(size_t)s_col[g][i] * F]);
        if (r != cur) {
            if (cur >= 0) atomicAdd(&dst[(size_t)cur * F + f], acc);
            cur = r;
            acc = 0.f;
        }
        acc += v;
    }
    if (cur >= 0) atomicAdd(&dst[(size_t)cur * F + f], acc);
}

// ===========================================================================
extern "C" void kernel_launch(void* const* d_in, const int* in_sizes, int n_in,
                              void* d_out, int out_size)
{
    const float* x   = (const float*)d_in[0];
    const float* w1  = (const float*)d_in[1];
    const float* b1  = (const float*)d_in[2];
    const float* w2  = (const float*)d_in[3];
    const float* b2  = (const float*)d_in[4];
    const float* ew  = (const float*)d_in[5];
    const int*   row = (const int*)d_in[6];
    const int*   col = (const int*)d_in[7];

    const int nhid  = in_sizes[2];            // 256
    const int nout  = in_sizes[4];            // 64
    const int nfeat = in_sizes[1] / nhid;     // 512
    const int n     = in_sizes[0] / nfeat;    // 50000
    const int E     = in_sizes[5];            // 800000

    void *p1, *p2, *p3, *p4, *p5;
    cudaGetSymbolAddress(&p1, g_h1);
    cudaGetSymbolAddress(&p2, g_h2);
    cudaGetSymbolAddress(&p3, g_h3);
    cudaGetSymbolAddress(&p4, g_w1t);
    cudaGetSymbolAddress(&p5, g_w2t);
    float* h1  = (float*)p1;
    float* h2  = (float*)p2;
    float* h3  = (float*)p3;
    float* w1t = (float*)p4;
    float* w2t = (float*)p5;
    float* out = (float*)d_out;

    const int tilesM = (n + 127) / 128;                   // 391

    // 0) both W transposes (+ tf32 RN rounding), single launch
    {
        int sz1 = nfeat * nhid, sz2 = nhid * nout;
        transpose_round2<<<(sz1 + sz2 + 255) / 256, 256>>>(
            w1, w1t, w2, w2t, sz1, nhid, nfeat, sz2, nout, nhid);
    }

    // 1) h1 = x @ W1   (mma.sync tf32; A rounded in registers)
    {
        dim3 grid(nhid / 128, tilesM);
        gemm_mma<128, 4, true><<<grid, 256>>>(x, w1t, h1, n, nfeat, nhid);
    }

    // 2) h2 = b1 + scatter(edge_w * h1[col]) into row
    {
        int total4 = n * nhid / 4;
        init_bias4<<<(total4 + 255) / 256, 256>>>(
            (float4*)h2, (const float4*)b1, total4, nhid / 4 - 1);
        spmm_scatter<256, 256, 1><<<(E + 255) / 256, 256>>>(h1, ew, row, col, h2, E);
    }

    // 3) h2 = rna_tf32(relu(h2)) in place; h3 = h2 @ W2
    {
        int n4 = n * nhid / 4;
        relu_round4<<<(n4 + 255) / 256, 256>>>(h2, n4);
        dim3 grid(nout / 64, tilesM);
        gemm_mma<64, 2, false><<<grid, 256>>>(h2, w2t, h3, n, nhid, nout);
    }

    // 4) out = b2 + scatter(edge_w * h3[col])
    {
        int total4 = n * nout / 4;
        init_bias4<<<(total4 + 255) / 256, 256>>>(
            (float4*)out, (const float4*)b2, total4, nout / 4 - 1);
        spmm_scatter<64, 256, 4><<<(E + 1023) / 1024, 256>>>(h3, ew, row, col, out, E);
    }
}

// round 5
// speedup vs baseline: 2.1868x; 1.1363x over previous
#include <cuda_runtime.h>
#include <cstdint>

// Problem constants (fixed by dataset)
#define MAXN   50000
#define NFEAT  512
#define FHID   256
#define FOUT   64

// Scratch (device globals: allocation-free per harness rules)
__device__ float g_h1 [MAXN * FHID];    // x @ W1
__device__ float g_h2 [MAXN * FHID];    // spmm(h1) + b1  (relu+rna applied on read in GEMM2)
__device__ float g_h3 [MAXN * FOUT];    // relu(h2) @ W2
__device__ float g_w1t[FHID * NFEAT];   // W1^T, tf32-rounded
__device__ float g_w2t[FOUT * FHID];    // W2^T, tf32-rounded

// ===========================================================================
// helpers
// ===========================================================================
__device__ __forceinline__ uint32_t smem_u32(const void* p) {
    uint32_t a;
    asm("{ .reg .u64 t; cvta.to.shared.u64 t, %1; cvt.u32.u64 %0, t; }"
        : "=r"(a) : "l"(p));
    return a;
}
__device__ __forceinline__ float rna_tf32(float f) {
    uint32_t u;
    asm("cvt.rna.tf32.f32 %0, %1;" : "=r"(u) : "f"(f));
    return __uint_as_float(u);
}
__device__ __forceinline__ void cp16(uint32_t dst, const void* src) {
    asm volatile("cp.async.cg.shared.global [%0], [%1], 16;"
                 :: "r"(dst), "l"(src) : "memory");
}
#define CP_COMMIT() asm volatile("cp.async.commit_group;" ::: "memory")
#define CP_WAIT0()  asm volatile("cp.async.wait_group 0;" ::: "memory")

// vectorized global reduction (PTX 8.1+, sm_90+ base feature)
__device__ __forceinline__ void red4(float* addr, float4 v) {
    asm volatile("red.global.add.v4.f32 [%0], {%1,%2,%3,%4};"
                 :: "l"(addr), "f"(v.x), "f"(v.y), "f"(v.z), "f"(v.w) : "memory");
}

// mma.sync m16n8k8 tf32 (base PTX, works on compute_103 target)
__device__ __forceinline__ void mma8(float* d, const uint32_t* a, const uint32_t* b) {
    asm volatile(
        "mma.sync.aligned.m16n8k8.row.col.f32.tf32.tf32.f32 "
        "{%0,%1,%2,%3}, {%4,%5,%6,%7}, {%8,%9}, {%0,%1,%2,%3};"
        : "+f"(d[0]), "+f"(d[1]), "+f"(d[2]), "+f"(d[3])
        : "r"(a[0]), "r"(a[1]), "r"(a[2]), "r"(a[3]), "r"(b[0]), "r"(b[1]));
}

// ===========================================================================
// tf32 tensor-core GEMM:  C[M, Ntot] = op(A)[M,K] @ Bt[Ntot,K]^T
//   AMODE: 0 = passthrough, 1 = rna-tf32 round, 2 = relu + rna-tf32 round
//   BM=128, BN template, BK=16; 256 threads = 8 warps (2M x 4N);
//   A register-staged, B via cp.async (pre-rounded); double-buffered SMEM.
// ===========================================================================
template<int BN, int WNT, int AMODE>
__global__ void __launch_bounds__(256)
gemm_mma(const float* __restrict__ A, const float* __restrict__ Bt,
         float* __restrict__ C, int M, int K, int Ntot)
{
    constexpr int BM = 128, BK = 16, LDS = 20;
    constexpr int NBI = (BN * BK / 4) / 256;      // B float4 per thread (2 or 1)
    __shared__ float As[2][BM * LDS];
    __shared__ float Bs[2][BN * LDS];

    const int tid  = threadIdx.x;
    const int lane = tid & 31, wid = tid >> 5;
    const int g    = lane >> 2, tig = lane & 3;
    const int wm0  = (wid >> 2) * 64;             // warp M origin (0/64)
    const int wn0  = (wid & 3) * (BN / 4);        // warp N origin
    const int blockM = blockIdx.y * BM;
    const int blockN = blockIdx.x * BN;

    const int arow = tid >> 2;                    // 0..63  (A rows: arow, arow+64)
    const int aq   = tid & 3;                     // which float4 within 16-col row

    float acc[4][WNT][4];
    #pragma unroll
    for (int mt = 0; mt < 4; mt++)
        #pragma unroll
        for (int nt = 0; nt < WNT; nt++)
            #pragma unroll
            for (int i = 0; i < 4; i++) acc[mt][nt][i] = 0.f;

    auto ldgA = [&](int c, float4* av) {
        const int k0 = c * BK;
        #pragma unroll
        for (int i = 0; i < 2; i++) {
            int r = blockM + arow + i * 64;
            if (r < M)
                av[i] = *reinterpret_cast<const float4*>(&A[(size_t)r * K + k0 + aq * 4]);
            else
                av[i] = make_float4(0.f, 0.f, 0.f, 0.f);
        }
    };
    auto stsA = [&](int buf, float4* av) {
        #pragma unroll
        for (int i = 0; i < 2; i++) {
            float4 v = av[i];
            if (AMODE == 2) {
                v.x = fmaxf(v.x, 0.f); v.y = fmaxf(v.y, 0.f);
                v.z = fmaxf(v.z, 0.f); v.w = fmaxf(v.w, 0.f);
            }
            if (AMODE >= 1) {
                v.x = rna_tf32(v.x); v.y = rna_tf32(v.y);
                v.z = rna_tf32(v.z); v.w = rna_tf32(v.w);
            }
            *reinterpret_cast<float4*>(&As[buf][(arow + i * 64) * LDS + aq * 4]) = v;
        }
    };
    auto cpB = [&](int c, int buf) {
        const int k0 = c * BK;
        #pragma unroll
        for (int i = 0; i < NBI; i++) {
            int u = tid + i * 256;
            int r = u >> 2, q = u & 3;
            cp16(smem_u32(&Bs[buf][r * LDS + q * 4]),
                 &Bt[(size_t)(blockN + r) * K + k0 + q * 4]);
        }
        CP_COMMIT();
    };
    auto compute = [&](int buf) {
        #pragma unroll
        for (int ks = 0; ks < 2; ks++) {
            uint32_t a[4][4], b[WNT][2];
            #pragma unroll
            for (int mt = 0; mt < 4; mt++) {
                const float* p0 = &As[buf][(wm0 + mt * 16 + g) * LDS + ks * 8];
                const float* p1 = p0 + 8 * LDS;
                a[mt][0] = __float_as_uint(p0[tig]);
                a[mt][2] = __float_as_uint(p0[tig + 4]);
                a[mt][1] = __float_as_uint(p1[tig]);
                a[mt][3] = __float_as_uint(p1[tig + 4]);
            }
            #pragma unroll
            for (int nt = 0; nt < WNT; nt++) {
                const float* pb = &Bs[buf][(wn0 + nt * 8 + g) * LDS + ks * 8];
                b[nt][0] = __float_as_uint(pb[tig]);
                b[nt][1] = __float_as_uint(pb[tig + 4]);
            }
            #pragma unroll
            for (int mt = 0; mt < 4; mt++)
                #pragma unroll
                for (int nt = 0; nt < WNT; nt++)
                    mma8(acc[mt][nt], a[mt], b[nt]);
        }
    };

    // prologue: fill buffer 0
    {
        float4 av[2];
        ldgA(0, av);
        cpB(0, 0);
        stsA(0, av);
        CP_WAIT0();
        __syncthreads();
    }

    const int NC = K / BK;
    for (int c = 0; c < NC; c++) {
        float4 av[2];
        const bool more = (c + 1 < NC);
        if (more) {
            ldgA(c + 1, av);           // global latency overlapped with compute
            cpB(c + 1, (c + 1) & 1);
        }
        compute(c & 1);
        if (more) {
            stsA((c + 1) & 1, av);
            CP_WAIT0();
            __syncthreads();
        }
    }

    // epilogue
    #pragma unroll
    for (int mt = 0; mt < 4; mt++) {
        int r0 = blockM + wm0 + mt * 16 + g;
        int r1 = r0 + 8;
        #pragma unroll
        for (int nt = 0; nt < WNT; nt++) {
            int cb = blockN + wn0 + nt * 8 + 2 * tig;
            if (r0 < M)
                *reinterpret_cast<float2*>(&C[(size_t)r0 * Ntot + cb]) =
                    make_float2(acc[mt][nt][0], acc[mt][nt][1]);
            if (r1 < M)
                *reinterpret_cast<float2*>(&C[(size_t)r1 * Ntot + cb]) =
                    make_float2(acc[mt][nt][2], acc[mt][nt][3]);
        }
    }
}

// ===========================================================================
// Elementwise kernels
// ===========================================================================
// Both weight transposes (+ tf32 RN rounding) in one launch.
__global__ void transpose_round2(const float* __restrict__ w1, float* __restrict__ w1t,
                                 const float* __restrict__ w2, float* __restrict__ w2t,
                                 int sz1, int n1, int k1, int sz2, int n2, int k2)
{
    int i = blockIdx.x * blockDim.x + threadIdx.x;
    if (i < sz1) {
        int k = i / n1, n = i % n1;
        w1t[(size_t)n * k1 + k] = rna_tf32(w1[i]);
    } else if (i < sz1 + sz2) {
        int j = i - sz1;
        int k = j / n2, n = j % n2;
        w2t[(size_t)n * k2 + k] = rna_tf32(w2[j]);
    }
}

// dst4[i] = bias4[i mod (F/4)], vectorized bias broadcast
__global__ void init_bias4(float4* __restrict__ dst, const float4* __restrict__ bias,
                           int total4, int fmask4)
{
    int i = blockIdx.x * blockDim.x + threadIdx.x;
    if (i < total4) dst[i] = bias[i & fmask4];
}

// ---------------------------------------------------------------------------
// SpMM scatter (float4 lanes): dst[row[e]] += edge_w[e] * src[col[e]],
// row sorted ascending.  T = F/4 threads per edge-group, G groups per block.
// Batched-4 LDG.128 gathers (MLP=4), register float4 accumulation across
// sorted-row runs, red.global.add.v4.f32 flush at row changes.
// ---------------------------------------------------------------------------
template<int F, int EPG, int G>
__global__ void __launch_bounds__((F / 4) * G)
spmm_scatter4(const float* __restrict__ src, const float* __restrict__ ew,
              const int* __restrict__ row, const int* __restrict__ col,
              float* __restrict__ dst, int E)
{
    constexpr int T = F / 4;
    __shared__ int   s_row[G][EPG];
    __shared__ uint2 s_cw[G][EPG];     // {col, edge_w bits}

    const int g = threadIdx.x / T;
    const int f = threadIdx.x % T;     // covers floats [4f, 4f+4)
    const long base = ((long)blockIdx.x * G + g) * EPG;

    long rem = (long)E - base;
    const int cnt = rem <= 0 ? 0 : (rem < EPG ? (int)rem : EPG);

    for (int i = f; i < cnt; i += T) {
        long e = base + i;
        s_row[g][i] = row[e];
        s_cw[g][i]  = make_uint2((unsigned)col[e], __float_as_uint(ew[e]));
    }
    __syncthreads();

    const float4* src4 = reinterpret_cast<const float4*>(src) + f;
    float4 acc = make_float4(0.f, 0.f, 0.f, 0.f);
    int    cur = -1;

    int i = 0;
    const int full = cnt & ~3;
    for (; i < full; i += 4) {
        int rr[4]; float w[4]; float4 v[4];
        #pragma unroll
        for (int j = 0; j < 4; j++) {              // 4 LDG.128 in flight
            rr[j] = s_row[g][i + j];
            uint2 cw = s_cw[g][i + j];
            w[j] = __uint_as_float(cw.y);
            v[j] = __ldg(&src4[(size_t)cw.x * T]);
        }
        #pragma unroll
        for (int j = 0; j < 4; j++) {              // register-only scan
            if (rr[j] != cur) {
                if (cur >= 0) red4(&dst[(size_t)cur * F + 4 * f], acc);
                cur = rr[j];
                acc = make_float4(0.f, 0.f, 0.f, 0.f);
            }
            acc.x = fmaf(w[j], v[j].x, acc.x);
            acc.y = fmaf(w[j], v[j].y, acc.y);
            acc.z = fmaf(w[j], v[j].z, acc.z);
            acc.w = fmaf(w[j], v[j].w, acc.w);
        }
    }
    for (; i < cnt; i++) {
        int   r = s_row[g][i];
        uint2 cw = s_cw[g][i];
        float w  = __uint_as_float(cw.y);
        float4 v = __ldg(&src4[(size_t)cw.x * T]);
        if (r != cur) {
            if (cur >= 0) red4(&dst[(size_t)cur * F + 4 * f], acc);
            cur = r;
            acc = make_float4(0.f, 0.f, 0.f, 0.f);
        }
        acc.x = fmaf(w, v.x, acc.x);
        acc.y = fmaf(w, v.y, acc.y);
        acc.z = fmaf(w, v.z, acc.z);
        acc.w = fmaf(w, v.w, acc.w);
    }
    if (cur >= 0) red4(&dst[(size_t)cur * F + 4 * f], acc);
}

// ===========================================================================
extern "C" void kernel_launch(void* const* d_in, const int* in_sizes, int n_in,
                              void* d_out, int out_size)
{
    const float* x   = (const float*)d_in[0];
    const float* w1  = (const float*)d_in[1];
    const float* b1  = (const float*)d_in[2];
    const float* w2  = (const float*)d_in[3];
    const float* b2  = (const float*)d_in[4];
    const float* ew  = (const float*)d_in[5];
    const int*   row = (const int*)d_in[6];
    const int*   col = (const int*)d_in[7];

    const int nhid  = in_sizes[2];            // 256
    const int nout  = in_sizes[4];            // 64
    const int nfeat = in_sizes[1] / nhid;     // 512
    const int n     = in_sizes[0] / nfeat;    // 50000
    const int E     = in_sizes[5];            // 800000

    void *p1, *p2, *p3, *p4, *p5;
    cudaGetSymbolAddress(&p1, g_h1);
    cudaGetSymbolAddress(&p2, g_h2);
    cudaGetSymbolAddress(&p3, g_h3);
    cudaGetSymbolAddress(&p4, g_w1t);
    cudaGetSymbolAddress(&p5, g_w2t);
    float* h1  = (float*)p1;
    float* h2  = (float*)p2;
    float* h3  = (float*)p3;
    float* w1t = (float*)p4;
    float* w2t = (float*)p5;
    float* out = (float*)d_out;

    const int tilesM = (n + 127) / 128;                   // 391

    // 0) both W transposes (+ tf32 RN rounding), single launch
    {
        int sz1 = nfeat * nhid, sz2 = nhid * nout;
        transpose_round2<<<(sz1 + sz2 + 255) / 256, 256>>>(
            w1, w1t, w2, w2t, sz1, nhid, nfeat, sz2, nout, nhid);
    }

    // 1) h1 = x @ W1   (mma.sync tf32; A rna-rounded in registers)
    {
        dim3 grid(nhid / 128, tilesM);
        gemm_mma<128, 4, 1><<<grid, 256>>>(x, w1t, h1, n, nfeat, nhid);
    }

    // 2) h2 = b1 + scatter(edge_w * h1[col]) into row
    {
        int total4 = n * nhid / 4;
        init_bias4<<<(total4 + 255) / 256, 256>>>(
            (float4*)h2, (const float4*)b1, total4, nhid / 4 - 1);
        // F=256: T=64, G=4, EPG=256 -> 1024 edges/block
        spmm_scatter4<256, 256, 4><<<(E + 1023) / 1024, 256>>>(h1, ew, row, col, h2, E);
    }

    // 3) h3 = relu(h2) @ W2   (relu + rna fused into A-register path)
    {
        dim3 grid(nout / 64, tilesM);
        gemm_mma<64, 2, 2><<<grid, 256>>>(h2, w2t, h3, n, nhid, nout);
    }

    // 4) out = b2 + scatter(edge_w * h3[col])
    {
        int total4 = n * nout / 4;
        init_bias4<<<(total4 + 255) / 256, 256>>>(
            (float4*)out, (const float4*)b2, total4, nout / 4 - 1);
        // F=64: T=16, G=16, EPG=128 -> 2048 edges/block
        spmm_scatter4<64, 128, 16><<<(E + 2047) / 2048, 256>>>(h3, ew, row, col, out, E);
    }
}